// round 11
// baseline (speedup 1.0000x reference)
#include <cuda_runtime.h>
#include <math.h>
#include <stdint.h>

// Problem dims (fixed)
#define Bc 4
#define Lc 2048
#define Hc 8
#define Dc 64
#define Mc 256
#define CHK 64
#define NCH (Lc/CHK)         // 32
#define BH (Bc*Hc)           // 32
#define NROWS (Bc*Lc*Hc)     // 65536

#define NORMC 0.35355339059327373f   // 64^(-1/4)
#define RATIO 0.0625f                // 1/sqrt(256)
#define DIAGC 0.0625f                // 0.5 * 64^(-1/2)
#define KEPS  1e-4f
#define BETA  (RATIO*KEPS)

// ----- scratch (static device arrays; no allocation) -----
__device__ float g_qp [(size_t)BH*Lc*Mc];      // 64 MB [bh][l][m] query features
__device__ float g_E  [(size_t)BH*Lc*Mc];      // 64 MB exp(dash - diag) for keys
__device__ float g_S  [(size_t)BH*NCH*Mc*Dc];  // 64 MB chunk states [m][d] -> excl prefix
__device__ float g_z  [(size_t)BH*NCH*Mc];
__device__ float g_kmax[BH];

__device__ __forceinline__ void atomicMaxF(float* addr, float v){
    int old = __float_as_int(*addr);
    while (__int_as_float(old) < v){
        int assumed = old;
        old = atomicCAS((int*)addr, assumed, __float_as_int(v));
        if (old == assumed) break;
    }
}

// Fast exp on the FMA pipe (no MUFU). rel err ~1.5e-7 on our range.
// exp(x) = 2^t, t = x*log2e; magic-add round, degree-6 poly for 2^r, r in [-.5,.5]
__device__ __forceinline__ float fexp(float x){
    float t = x * 1.4426950408889634f;
    t = fminf(fmaxf(t, -120.f), 120.f);
    float fn = t + 12582912.f;                       // 1.5*2^23: RN to integer
    int   e  = __float_as_int(fn) - 0x4B400000;      // (int)rint(t)
    float n  = fn - 12582912.f;
    float r  = t - n;                                // [-0.5, 0.5]
    float p  = 1.53720378e-4f;
    p = fmaf(p, r, 1.33903036e-3f);
    p = fmaf(p, r, 9.61817248e-3f);
    p = fmaf(p, r, 5.55036329e-2f);
    p = fmaf(p, r, 2.40226507e-1f);
    p = fmaf(p, r, 6.93147182e-1f);
    p = fmaf(p, r, 1.0f);                            // 2^r
    return __int_as_float(__float_as_int(p) + (e << 23));
}

// fp32 -> tf32 (round-to-nearest), kept in a float register slot
__device__ __forceinline__ float tf32f(float f){
    uint32_t r;
    asm("cvt.rna.tf32.f32 %0, %1;" : "=r"(r) : "f"(f));
    return __uint_as_float(r);
}

__device__ __forceinline__ void mma_tf32(float& d0, float& d1, float& d2, float& d3,
                                         uint32_t a0, uint32_t a1, uint32_t a2, uint32_t a3,
                                         uint32_t b0, uint32_t b1){
    asm volatile("mma.sync.aligned.m16n8k8.row.col.f32.tf32.tf32.f32 "
        "{%0,%1,%2,%3}, {%4,%5,%6,%7}, {%8,%9}, {%0,%1,%2,%3};"
        : "+f"(d0), "+f"(d1), "+f"(d2), "+f"(d3)
        : "r"(a0), "r"(a1), "r"(a2), "r"(a3), "r"(b0), "r"(b1));
}

__global__ void init_kernel(){
    if (threadIdx.x < BH) g_kmax[threadIdx.x] = -3.0e38f;
}

// ============================================================
// K1: features. X:[B,L,H,D] -> dash = norm * X @ P^T
// queries: full feature (row-max stab) -> g_qp
// keys:    E = exp(dash - diag) -> g_E, atomic bh-max of dash
// exp via fexp (FMA pipe) — MUFU no longer the bottleneck.
// ============================================================
#define PT_S 260
#define XT_S 68

__global__ __launch_bounds__(256,2) void feat_kernel(const float* __restrict__ X,
                                                     const float* __restrict__ P,
                                                     int isQuery)
{
    extern __shared__ float sm[];
    float* Pt   = sm;
    float* xT   = Pt + 64*PT_S;
    float* ss_s = xT + 64*XT_S;
    const int tid = threadIdx.x;

    for (int i = tid; i < Mc*Dc; i += 256){
        int m = i >> 6, d = i & 63;
        Pt[d*PT_S + m] = P[i];
    }
    const int row0 = blockIdx.x * 64;
    const float* Xb = X + (size_t)row0 * Dc;
    for (int i = tid; i < 64*Dc; i += 256){
        int r = i >> 6, d = i & 63;
        xT[d*XT_S + r] = Xb[i];
    }
    __syncthreads();

    if (tid < 64){
        float s = 0.f;
        #pragma unroll
        for (int d = 0; d < 64; d++){ float xv = xT[d*XT_S + tid]; s += xv*xv; }
        ss_s[tid] = s;
    }

    const int ri = tid >> 5, mi = tid & 31;
    float acc[8][8];
    #pragma unroll
    for (int i = 0; i < 8; i++)
        #pragma unroll
        for (int j = 0; j < 8; j++) acc[i][j] = 0.f;

    #pragma unroll 4
    for (int d = 0; d < 64; d++){
        float4 x0 = *(const float4*)&xT[d*XT_S + ri*8];
        float4 x1 = *(const float4*)&xT[d*XT_S + ri*8 + 4];
        float4 p0 = *(const float4*)&Pt[d*PT_S + mi*4];
        float4 p1 = *(const float4*)&Pt[d*PT_S + 128 + mi*4];
        float xv[8] = {x0.x,x0.y,x0.z,x0.w,x1.x,x1.y,x1.z,x1.w};
        float pv[8] = {p0.x,p0.y,p0.z,p0.w,p1.x,p1.y,p1.z,p1.w};
        #pragma unroll
        for (int i = 0; i < 8; i++)
            #pragma unroll
            for (int j = 0; j < 8; j++) acc[i][j] += xv[i]*pv[j];
    }
    __syncthreads();

    #pragma unroll
    for (int i = 0; i < 8; i++){
        int r = ri*8 + i;
        float mx = -3.0e38f;
        #pragma unroll
        for (int j = 0; j < 8; j++){ acc[i][j] *= NORMC; mx = fmaxf(mx, acc[i][j]); }
        #pragma unroll
        for (int o = 16; o > 0; o >>= 1) mx = fmaxf(mx, __shfl_xor_sync(0xffffffffu, mx, o));

        int grow = row0 + r;
        int hh = grow & 7;
        int bl = grow >> 3;
        int b  = bl >> 11;
        int l  = bl & 2047;
        int bh = b*Hc + hh;
        float diag = DIAGC * ss_s[r];
        size_t drow = ((size_t)bh*Lc + l)*Mc;

        if (isQuery){
            float o0[4], o1[4];
            #pragma unroll
            for (int j = 0; j < 4; j++){
                o0[j] = RATIO * (fexp(acc[i][j]   - diag - mx) + KEPS);
                o1[j] = RATIO * (fexp(acc[i][j+4] - diag - mx) + KEPS);
            }
            *(float4*)&g_qp[drow + mi*4]       = make_float4(o0[0],o0[1],o0[2],o0[3]);
            *(float4*)&g_qp[drow + 128 + mi*4] = make_float4(o1[0],o1[1],o1[2],o1[3]);
        } else {
            float e0[4], e1[4];
            #pragma unroll
            for (int j = 0; j < 4; j++){
                e0[j] = fexp(acc[i][j]   - diag);
                e1[j] = fexp(acc[i][j+4] - diag);
            }
            *(float4*)&g_E[drow + mi*4]       = make_float4(e0[0],e0[1],e0[2],e0[3]);
            *(float4*)&g_E[drow + 128 + mi*4] = make_float4(e1[0],e1[1],e1[2],e1[3]);
            if (mi == 0) atomicMaxF(&g_kmax[bh], mx);
        }
    }
}

// ============================================================
// K3: per 64-chunk state. 2 blocks per chunk (m-halves of 128).
// kp = alpha*E + beta at staging.  S_c[m][d] = K'^T V, z_c = sum K'.
// ============================================================
#define VS 68
__global__ __launch_bounds__(256,3) void state_kernel(const float* __restrict__ V)
{
    extern __shared__ float sm[];
    float* kt = sm;              // [32 t][128 m]
    float* vt = kt + 32*128;     // [32 t][VS]
    const int tid = threadIdx.x;
    const int bi = blockIdx.x;
    const int bh = bi >> 6;
    const int rest = bi & 63;
    const int c = rest >> 1, half = rest & 1;
    const int b = bh >> 3, h = bh & 7;
    const float alpha = RATIO * fexp(-g_kmax[bh]);
    const int lbase = c*CHK;
    const int mh0 = half*128;
    const size_t base_lm = ((size_t)bh*Lc + lbase)*Mc + mh0;
    const size_t vbase = (((size_t)b*Lc + lbase)*Hc + h)*Dc;

    const int a = tid >> 3, bq = tid & 7;   // m rows a*4.., d cols {bq*4, 32+bq*4}
    float acc[4][8];
    float accZ[4];
    #pragma unroll
    for (int i = 0; i < 4; i++){
        accZ[i] = 0.f;
        #pragma unroll
        for (int j = 0; j < 8; j++) acc[i][j] = 0.f;
    }

    for (int t0 = 0; t0 < CHK; t0 += 32){
        __syncthreads();
        for (int i = tid; i < 1024; i += 256){
            int t = i >> 5, m4 = (i & 31) * 4;
            float4 ev = *(const float4*)&g_E[base_lm + (size_t)(t0 + t)*Mc + m4];
            float4 val;
            val.x = fmaf(alpha, ev.x, BETA);
            val.y = fmaf(alpha, ev.y, BETA);
            val.z = fmaf(alpha, ev.z, BETA);
            val.w = fmaf(alpha, ev.w, BETA);
            *(float4*)&kt[t*128 + m4] = val;
        }
        for (int i = tid; i < 512; i += 256){
            int t = i >> 4, d4 = (i & 15) * 4;
            *(float4*)&vt[t*VS + d4] =
                *(const float4*)&V[vbase + (size_t)(t0 + t)*(Hc*Dc) + d4];
        }
        __syncthreads();

        #pragma unroll 8
        for (int t = 0; t < 32; t++){
            float4 kf = *(const float4*)&kt[t*128 + a*4];
            float4 v0 = *(const float4*)&vt[t*VS + bq*4];
            float4 v1 = *(const float4*)&vt[t*VS + 32 + bq*4];
            float kv[4] = {kf.x, kf.y, kf.z, kf.w};
            float vv[8] = {v0.x,v0.y,v0.z,v0.w,v1.x,v1.y,v1.z,v1.w};
            #pragma unroll
            for (int i = 0; i < 4; i++){
                accZ[i] += kv[i];
                #pragma unroll
                for (int j = 0; j < 8; j++) acc[i][j] += kv[i]*vv[j];
            }
        }
    }

    const size_t Sbase = ((size_t)bh*NCH + c)*Mc*Dc + (size_t)mh0*Dc;
    #pragma unroll
    for (int i = 0; i < 4; i++){
        size_t o = Sbase + (size_t)(a*4 + i)*Dc;
        *(float4*)&g_S[o + bq*4]      = make_float4(acc[i][0],acc[i][1],acc[i][2],acc[i][3]);
        *(float4*)&g_S[o + 32 + bq*4] = make_float4(acc[i][4],acc[i][5],acc[i][6],acc[i][7]);
    }
    if (bq == 0){
        size_t zo = ((size_t)bh*NCH + c)*Mc + mh0 + a*4;
        #pragma unroll
        for (int i = 0; i < 4; i++) g_z[zo + i] = accZ[i];
    }
}

// ============================================================
// K4: exclusive prefix over 32 chunks — one independent chain per thread.
// grid = BH * (Mc*Dc/256) = 2048 blocks; full unroll -> 32 loads in flight.
// z chains (Mc per bh) folded into the first block of each bh-slice.
// ============================================================
__global__ __launch_bounds__(256) void prefix_kernel()
{
    const int bh = blockIdx.x >> 6;          // 64 blocks per bh
    const int sl = blockIdx.x & 63;
    const int tid = threadIdx.x;
    const int e = (sl << 8) + tid;           // element in [0, Mc*Dc)

    size_t idx = (size_t)bh*NCH*Mc*Dc + e;
    float run = 0.f;
    #pragma unroll
    for (int c2 = 0; c2 < NCH; c2++){
        float tmp = g_S[idx]; g_S[idx] = run; run += tmp; idx += (size_t)Mc*Dc;
    }
    if (sl == 0){
        size_t zi = (size_t)bh*NCH*Mc + tid;
        float zr = 0.f;
        #pragma unroll
        for (int c2 = 0; c2 < NCH; c2++){
            float tmp = g_z[zi]; g_z[zi] = zr; zr += tmp; zi += Mc;
        }
    }
}

// ============================================================
// K5: mma.sync tf32 output kernel. 1 block per 64-chunk (1024 blocks).
// 8 warps: warp (tg = w&3, ng = w>>2).
// GEMM1 (k = m, 4 m-tiles x 8 k-steps):
//   ng=0: A[16t x 64s] = Q'K'^T        (8 n-tiles)
//   ng=1: [numI | z] [16t x 72]        (9 n-tiles; tile 8 col 0 = denI)
// epilogue: mask A -> rowsum den; A,numI,denI -> smem; stage V.
// GEMM2 (k = s): num = numI + A V (each warp 16t x 32d).
// out = num / (den + denI)
// ============================================================
#define OP 68           // padded row length (68 floats = 272 B, 16B multiple)
__global__ __launch_bounds__(256,3) void out_kernel(const float* __restrict__ V,
                                                    float* __restrict__ Out)
{
    extern __shared__ float sm[];
    float* q_sm    = sm;            // [64 t][OP]  (aliased: A_sm after GEMM1)
    float* kp_sm   = sm + 64*OP;    // [64 s][OP]  (aliased: numI_sm)
    float* S_sm    = sm + 2*64*OP;  // [64 m][OP]  (aliased: v_sm)
    float* z_sm    = sm + 3*64*OP;          // [64]
    float* den_sm  = z_sm + 64;             // [64]
    float* denI_sm = den_sm + 64;           // [64]
    float* A_sm    = q_sm;
    float* numI_sm = kp_sm;
    float* v_sm    = S_sm;

    const int tid = threadIdx.x;
    const int w = tid >> 5, lane = tid & 31;
    const int tg = w & 3, ng = w >> 2;
    const int lr = lane >> 2, lc = lane & 3;
    const int bi = blockIdx.x;
    const int bh = bi >> 5, c = bi & 31;
    const int b = bh >> 3, h = bh & 7;
    const int lbase = c*CHK;
    const float alpha = RATIO * fexp(-g_kmax[bh]);

    const size_t qbase = ((size_t)bh*Lc + lbase)*Mc;
    const size_t Sb    = ((size_t)bh*NCH + c)*Mc*Dc;
    const size_t zbg   = ((size_t)bh*NCH + c)*Mc;
    const size_t vbase = (((size_t)b*Lc + lbase)*Hc + h)*Dc;

    const int t_lo = tg*16 + lr;
    const int t_hi = t_lo + 8;

    float acc[9][4];
    #pragma unroll
    for (int j = 0; j < 9; j++)
        #pragma unroll
        for (int r = 0; r < 4; r++) acc[j][r] = 0.f;

    // ================= GEMM1: loop over 4 m-tiles =================
    for (int m0 = 0; m0 < Mc; m0 += 64){
        __syncthreads();
        for (int i = tid; i < 1024; i += 256){
            int r = i >> 4, f4 = (i & 15)*4;
            float4 v = *(const float4*)&g_qp[qbase + (size_t)r*Mc + m0 + f4];
            *(float4*)&q_sm[r*OP + f4] =
                make_float4(tf32f(v.x), tf32f(v.y), tf32f(v.z), tf32f(v.w));
        }
        for (int i = tid; i < 1024; i += 256){
            int r = i >> 4, f4 = (i & 15)*4;
            float4 e = *(const float4*)&g_E[qbase + (size_t)r*Mc + m0 + f4];
            *(float4*)&kp_sm[r*OP + f4] =
                make_float4(tf32f(fmaf(alpha, e.x, BETA)), tf32f(fmaf(alpha, e.y, BETA)),
                            tf32f(fmaf(alpha, e.z, BETA)), tf32f(fmaf(alpha, e.w, BETA)));
        }
        for (int i = tid; i < 1024; i += 256){
            int r = i >> 4, f4 = (i & 15)*4;   // r = m row of tile
            float4 v = *(const float4*)&g_S[Sb + (size_t)(m0 + r)*Dc + f4];
            *(float4*)&S_sm[r*OP + f4] =
                make_float4(tf32f(v.x), tf32f(v.y), tf32f(v.z), tf32f(v.w));
        }
        if (tid < 64) z_sm[tid] = tf32f(g_z[zbg + m0 + tid]);
        __syncthreads();

        #pragma unroll
        for (int ks = 0; ks < 8; ks++){
            const int k0 = ks*8;
            const float* ar = &q_sm[t_lo*OP + k0 + lc];
            uint32_t a0 = __float_as_uint(ar[0]);
            uint32_t a1 = __float_as_uint(ar[8*OP]);
            uint32_t a2 = __float_as_uint(ar[4]);
            uint32_t a3 = __float_as_uint(ar[8*OP + 4]);
            if (ng == 0){
                #pragma unroll
                for (int j = 0; j < 8; j++){
                    uint32_t b0 = __float_as_uint(kp_sm[(j*8 + lr)*OP + k0 + lc]);
                    uint32_t b1 = __float_as_uint(kp_sm[(j*8 + lr)*OP + k0 + 4 + lc]);
                    mma_tf32(acc[j][0], acc[j][1], acc[j][2], acc[j][3],
                             a0, a1, a2, a3, b0, b1);
                }
            } else {
                #pragma unroll
                for (int j = 0; j < 8; j++){
                    uint32_t b0 = __float_as_uint(S_sm[(k0 + lc)*OP + j*8 + lr]);
                    uint32_t b1 = __float_as_uint(S_sm[(k0 + 4 + lc)*OP + j*8 + lr]);
                    mma_tf32(acc[j][0], acc[j][1], acc[j][2], acc[j][3],
                             a0, a1, a2, a3, b0, b1);
                }
                // z tile: col 0 = z, cols 1..7 = 0
                uint32_t b0 = (lr == 0) ? __float_as_uint(z_sm[k0 + lc]) : 0u;
                uint32_t b1 = (lr == 0) ? __float_as_uint(z_sm[k0 + 4 + lc]) : 0u;
                mma_tf32(acc[8][0], acc[8][1], acc[8][2], acc[8][3],
                         a0, a1, a2, a3, b0, b1);
            }
        }
    }
    __syncthreads();   // all GEMM1 reads done; aliases become writable

    // ================= epilogue =================
    if (ng == 0){
        float sum_lo = 0.f, sum_hi = 0.f;
        #pragma unroll
        for (int j = 0; j < 8; j++){
            int s0 = j*8 + lc*2;
            float v0 = (s0     <= t_lo) ? acc[j][0] : 0.f;
            float v1 = (s0 + 1 <= t_lo) ? acc[j][1] : 0.f;
            float v2 = (s0     <= t_hi) ? acc[j][2] : 0.f;
            float v3 = (s0 + 1 <= t_hi) ? acc[j][3] : 0.f;
            sum_lo += v0 + v1;
            sum_hi += v2 + v3;
            A_sm[t_lo*OP + s0]     = tf32f(v0);
            A_sm[t_lo*OP + s0 + 1] = tf32f(v1);
            A_sm[t_hi*OP + s0]     = tf32f(v2);
            A_sm[t_hi*OP + s0 + 1] = tf32f(v3);
        }
        sum_lo += __shfl_xor_sync(0xffffffffu, sum_lo, 1);
        sum_lo += __shfl_xor_sync(0xffffffffu, sum_lo, 2);
        sum_hi += __shfl_xor_sync(0xffffffffu, sum_hi, 1);
        sum_hi += __shfl_xor_sync(0xffffffffu, sum_hi, 2);
        if (lc == 0){ den_sm[t_lo] = sum_lo; den_sm[t_hi] = sum_hi; }
    } else {
        #pragma unroll
        for (int j = 0; j < 8; j++){
            int d0 = j*8 + lc*2;
            numI_sm[t_lo*OP + d0]     = acc[j][0];
            numI_sm[t_lo*OP + d0 + 1] = acc[j][1];
            numI_sm[t_hi*OP + d0]     = acc[j][2];
            numI_sm[t_hi*OP + d0 + 1] = acc[j][3];
        }
        if (lc == 0){ denI_sm[t_lo] = acc[8][0]; denI_sm[t_hi] = acc[8][2]; }
    }
    // stage V (tf32) into v_sm (aliases S_sm)
    for (int i = tid; i < 1024; i += 256){
        int s = i >> 4, f4 = (i & 15)*4;
        float4 v = *(const float4*)&V[vbase + (size_t)s*(Hc*Dc) + f4];
        *(float4*)&v_sm[s*OP + f4] =
            make_float4(tf32f(v.x), tf32f(v.y), tf32f(v.z), tf32f(v.w));
    }
    __syncthreads();

    // ================= GEMM2: num = numI + A V =================
    const int d0base = ng*32;
    float cc[4][4];
    #pragma unroll
    for (int j = 0; j < 4; j++){
        int d0 = d0base + j*8 + lc*2;
        cc[j][0] = numI_sm[t_lo*OP + d0];
        cc[j][1] = numI_sm[t_lo*OP + d0 + 1];
        cc[j][2] = numI_sm[t_hi*OP + d0];
        cc[j][3] = numI_sm[t_hi*OP + d0 + 1];
    }
    #pragma unroll
    for (int ks = 0; ks < 8; ks++){
        const int s0 = ks*8;
        const float* ar = &A_sm[t_lo*OP + s0 + lc];
        uint32_t a0 = __float_as_uint(ar[0]);
        uint32_t a1 = __float_as_uint(ar[8*OP]);
        uint32_t a2 = __float_as_uint(ar[4]);
        uint32_t a3 = __float_as_uint(ar[8*OP + 4]);
        #pragma unroll
        for (int j = 0; j < 4; j++){
            int d0 = d0base + j*8;
            uint32_t b0 = __float_as_uint(v_sm[(s0 + lc)*OP + d0 + lr]);
            uint32_t b1 = __float_as_uint(v_sm[(s0 + 4 + lc)*OP + d0 + lr]);
            mma_tf32(cc[j][0], cc[j][1], cc[j][2], cc[j][3],
                     a0, a1, a2, a3, b0, b1);
        }
    }

    // ================= normalize + store =================
    float denL = den_sm[t_lo] + denI_sm[t_lo];
    float denH = den_sm[t_hi] + denI_sm[t_hi];
    if (fabsf(denL) <= 1e-6f) denL += 2e-6f;
    if (fabsf(denH) <= 1e-6f) denH += 2e-6f;
    float invL = 1.0f / denL;
    float invH = 1.0f / denH;

    float* orowL = Out + (((size_t)b*Lc + lbase + t_lo)*Hc + h)*Dc;
    float* orowH = Out + (((size_t)b*Lc + lbase + t_hi)*Hc + h)*Dc;
    #pragma unroll
    for (int j = 0; j < 4; j++){
        int d0 = d0base + j*8 + lc*2;
        *(float2*)&orowL[d0] = make_float2(cc[j][0]*invL, cc[j][1]*invL);
        *(float2*)&orowH[d0] = make_float2(cc[j][2]*invH, cc[j][3]*invH);
    }
}

// ============================================================
extern "C" void kernel_launch(void* const* d_in, const int* in_sizes, int n_in,
                              void* d_out, int out_size)
{
    const float* Q = (const float*)d_in[0];
    const float* K = (const float*)d_in[1];
    const float* V = (const float*)d_in[2];
    const float* P = (const float*)d_in[3];
    float* O = (float*)d_out;

    const int SM1 = (64*PT_S + 64*XT_S + 64) * 4;   // ~84 KB
    const int SM3 = (32*128 + 32*VS) * 4;           // ~24.5 KB
    const int SM5 = (3*64*OP + 64*3) * 4;           // ~53 KB

    cudaFuncSetAttribute(feat_kernel, cudaFuncAttributeMaxDynamicSharedMemorySize, SM1);
    cudaFuncSetAttribute(out_kernel,  cudaFuncAttributeMaxDynamicSharedMemorySize, SM5);

    init_kernel<<<1, 32>>>();
    feat_kernel<<<NROWS/64, 256, SM1>>>(Q, P, 1);
    feat_kernel<<<NROWS/64, 256, SM1>>>(K, P, 0);
    state_kernel<<<BH*NCH*2, 256, SM3>>>(V);
    prefix_kernel<<<BH*64, 256>>>();
    out_kernel<<<BH*NCH, 256, SM5>>>(V, O);
}

// round 12
// speedup vs baseline: 1.2099x; 1.2099x over previous
#include <cuda_runtime.h>
#include <math.h>
#include <stdint.h>

// Problem dims (fixed)
#define Bc 4
#define Lc 2048
#define Hc 8
#define Dc 64
#define Mc 256
#define CHK 64
#define NCH (Lc/CHK)         // 32
#define BH (Bc*Hc)           // 32
#define NROWS (Bc*Lc*Hc)     // 65536

#define NORMC 0.35355339059327373f   // 64^(-1/4)
#define RATIO 0.0625f                // 1/sqrt(256)
#define DIAGC 0.0625f                // 0.5 * 64^(-1/2)
#define KEPS  1e-4f
#define BETA  (RATIO*KEPS)

// ----- scratch (static device arrays; no allocation) -----
__device__ float g_qp [(size_t)BH*Lc*Mc];      // 64 MB [bh][l][m] query features
__device__ float g_E  [(size_t)BH*Lc*Mc];      // 64 MB exp(dash - diag) for keys
__device__ float g_S  [(size_t)BH*NCH*Mc*Dc];  // 64 MB chunk states [m][d] -> excl prefix
__device__ float g_z  [(size_t)BH*NCH*Mc];
__device__ float g_kmax[BH];

__device__ __forceinline__ void atomicMaxF(float* addr, float v){
    int old = __float_as_int(*addr);
    while (__int_as_float(old) < v){
        int assumed = old;
        old = atomicCAS((int*)addr, assumed, __float_as_int(v));
        if (old == assumed) break;
    }
}

// fp32 -> tf32 (round-to-nearest), kept in a float register slot
__device__ __forceinline__ float tf32f(float f){
    uint32_t r;
    asm("cvt.rna.tf32.f32 %0, %1;" : "=r"(r) : "f"(f));
    return __uint_as_float(r);
}

__device__ __forceinline__ void mma_tf32(float& d0, float& d1, float& d2, float& d3,
                                         uint32_t a0, uint32_t a1, uint32_t a2, uint32_t a3,
                                         uint32_t b0, uint32_t b1){
    asm volatile("mma.sync.aligned.m16n8k8.row.col.f32.tf32.tf32.f32 "
        "{%0,%1,%2,%3}, {%4,%5,%6,%7}, {%8,%9}, {%0,%1,%2,%3};"
        : "+f"(d0), "+f"(d1), "+f"(d2), "+f"(d3)
        : "r"(a0), "r"(a1), "r"(a2), "r"(a3), "r"(b0), "r"(b1));
}

__global__ void init_kernel(){
    if (threadIdx.x < BH) g_kmax[threadIdx.x] = -3.0e38f;
}

// ============================================================
// K1: features. 128 rows per block, 2 passes sharing one staged P.
// queries: full feature (row-max stab) -> g_qp
// keys:    E = exp(dash - diag) -> g_E, atomic bh-max of dash
// ============================================================
#define PT_S 260
#define XT_S 68

__global__ __launch_bounds__(256,2) void feat_kernel(const float* __restrict__ X,
                                                     const float* __restrict__ P,
                                                     int isQuery)
{
    extern __shared__ float sm[];
    float* Pt   = sm;
    float* xT   = Pt + 64*PT_S;
    float* ss_s = xT + 64*XT_S;
    const int tid = threadIdx.x;

    for (int i = tid; i < Mc*Dc; i += 256){
        int m = i >> 6, d = i & 63;
        Pt[d*PT_S + m] = P[i];
    }

    const int ri = tid >> 5, mi = tid & 31;
    const int blk_row0 = blockIdx.x * 128;

    for (int pass = 0; pass < 2; pass++){
        __syncthreads();   // P ready (p0) / previous pass reads done (p1)
        const int row0 = blk_row0 + pass*64;
        const float* Xb = X + (size_t)row0 * Dc;
        for (int i = tid; i < 64*Dc; i += 256){
            int r = i >> 6, d = i & 63;
            xT[d*XT_S + r] = Xb[i];
        }
        __syncthreads();

        if (tid < 64){
            float s = 0.f;
            #pragma unroll
            for (int d = 0; d < 64; d++){ float xv = xT[d*XT_S + tid]; s += xv*xv; }
            ss_s[tid] = s;
        }

        float acc[8][8];
        #pragma unroll
        for (int i = 0; i < 8; i++)
            #pragma unroll
            for (int j = 0; j < 8; j++) acc[i][j] = 0.f;

        #pragma unroll 4
        for (int d = 0; d < 64; d++){
            float4 x0 = *(const float4*)&xT[d*XT_S + ri*8];
            float4 x1 = *(const float4*)&xT[d*XT_S + ri*8 + 4];
            float4 p0 = *(const float4*)&Pt[d*PT_S + mi*4];
            float4 p1 = *(const float4*)&Pt[d*PT_S + 128 + mi*4];
            float xv[8] = {x0.x,x0.y,x0.z,x0.w,x1.x,x1.y,x1.z,x1.w};
            float pv[8] = {p0.x,p0.y,p0.z,p0.w,p1.x,p1.y,p1.z,p1.w};
            #pragma unroll
            for (int i = 0; i < 8; i++)
                #pragma unroll
                for (int j = 0; j < 8; j++) acc[i][j] += xv[i]*pv[j];
        }
        __syncthreads();   // ss_s ready; GEMM reads of xT done

        #pragma unroll
        for (int i = 0; i < 8; i++){
            int r = ri*8 + i;
            float mx = -3.0e38f;
            #pragma unroll
            for (int j = 0; j < 8; j++){ acc[i][j] *= NORMC; mx = fmaxf(mx, acc[i][j]); }
            #pragma unroll
            for (int o = 16; o > 0; o >>= 1) mx = fmaxf(mx, __shfl_xor_sync(0xffffffffu, mx, o));

            int grow = row0 + r;
            int hh = grow & 7;
            int bl = grow >> 3;
            int b  = bl >> 11;
            int l  = bl & 2047;
            int bh = b*Hc + hh;
            float diag = DIAGC * ss_s[r];
            size_t drow = ((size_t)bh*Lc + l)*Mc;

            if (isQuery){
                float o0[4], o1[4];
                #pragma unroll
                for (int j = 0; j < 4; j++){
                    o0[j] = RATIO * (__expf(acc[i][j]   - diag - mx) + KEPS);
                    o1[j] = RATIO * (__expf(acc[i][j+4] - diag - mx) + KEPS);
                }
                *(float4*)&g_qp[drow + mi*4]       = make_float4(o0[0],o0[1],o0[2],o0[3]);
                *(float4*)&g_qp[drow + 128 + mi*4] = make_float4(o1[0],o1[1],o1[2],o1[3]);
            } else {
                float e0[4], e1[4];
                #pragma unroll
                for (int j = 0; j < 4; j++){
                    e0[j] = __expf(acc[i][j]   - diag);
                    e1[j] = __expf(acc[i][j+4] - diag);
                }
                *(float4*)&g_E[drow + mi*4]       = make_float4(e0[0],e0[1],e0[2],e0[3]);
                *(float4*)&g_E[drow + 128 + mi*4] = make_float4(e1[0],e1[1],e1[2],e1[3]);
                if (mi == 0) atomicMaxF(&g_kmax[bh], mx);
            }
        }
    }
}

// ============================================================
// K3 v3: state via mma.sync tf32. 2 blocks per chunk (m-halves of 128).
// A[m][t] = kp (tf32), B[t][d] = V (tf32). S_c[m][d] += A x B over t=64.
// z computed exactly with scalar sums (fp32 kp).
// Fragment mapping identical to the verified out_kernel pattern.
// ============================================================
#define KTP 136        // kt row stride: bank(136t+m)=8t+m -> conflict-free frags
#define VTP 72         // vt row stride: bank(72t+d)=8t+d -> conflict-free frags
__global__ __launch_bounds__(256,3) void state_kernel(const float* __restrict__ V)
{
    extern __shared__ float sm[];
    float* kt = sm;              // [64 t][KTP]  (m cols 0..127), tf32 values
    float* vt = kt + 64*KTP;     // [64 t][VTP]  (d cols 0..63), tf32 values
    const int tid = threadIdx.x;
    const int w = tid >> 5, lane = tid & 31;
    const int lr = lane >> 2, lc = lane & 3;
    const int bi = blockIdx.x;
    const int bh = bi >> 6;
    const int rest = bi & 63;
    const int c = rest >> 1, half = rest & 1;
    const int b = bh >> 3, h = bh & 7;
    const float alpha = RATIO * __expf(-g_kmax[bh]);
    const int lbase = c*CHK;
    const int mh0 = half*128;
    const size_t base_lm = ((size_t)bh*Lc + lbase)*Mc + mh0;
    const size_t vbase = (((size_t)b*Lc + lbase)*Hc + h)*Dc;

    // stage kp (tf32): 64 t x 128 m
    for (int i = tid; i < 2048; i += 256){
        int t = i >> 5, m4 = (i & 31) * 4;
        float4 ev = *(const float4*)&g_E[base_lm + (size_t)t*Mc + m4];
        *(float4*)&kt[t*KTP + m4] =
            make_float4(tf32f(fmaf(alpha, ev.x, BETA)), tf32f(fmaf(alpha, ev.y, BETA)),
                        tf32f(fmaf(alpha, ev.z, BETA)), tf32f(fmaf(alpha, ev.w, BETA)));
    }
    // stage V (tf32): 64 t x 64 d
    for (int i = tid; i < 1024; i += 256){
        int t = i >> 4, d4 = (i & 15) * 4;
        float4 v = *(const float4*)&V[vbase + (size_t)t*(Hc*Dc) + d4];
        *(float4*)&vt[t*VTP + d4] =
            make_float4(tf32f(v.x), tf32f(v.y), tf32f(v.z), tf32f(v.w));
    }
    __syncthreads();

    // warp w owns m rows [w*16, w*16+16); n = d (8 tiles of 8); k = t (8 steps)
    const int wm = w*16;
    float acc[8][4];
    #pragma unroll
    for (int j = 0; j < 8; j++)
        #pragma unroll
        for (int r = 0; r < 4; r++) acc[j][r] = 0.f;

    #pragma unroll
    for (int ks = 0; ks < 8; ks++){
        const int k0 = ks*8;
        uint32_t a0 = __float_as_uint(kt[(k0 + lc)*KTP     + wm + lr]);
        uint32_t a1 = __float_as_uint(kt[(k0 + lc)*KTP     + wm + 8 + lr]);
        uint32_t a2 = __float_as_uint(kt[(k0 + 4 + lc)*KTP + wm + lr]);
        uint32_t a3 = __float_as_uint(kt[(k0 + 4 + lc)*KTP + wm + 8 + lr]);
        #pragma unroll
        for (int j = 0; j < 8; j++){
            uint32_t b0 = __float_as_uint(vt[(k0 + lc)*VTP     + j*8 + lr]);
            uint32_t b1 = __float_as_uint(vt[(k0 + 4 + lc)*VTP + j*8 + lr]);
            mma_tf32(acc[j][0], acc[j][1], acc[j][2], acc[j][3],
                     a0, a1, a2, a3, b0, b1);
        }
    }

    // store S: c0=(m=wm+lr, d=j*8+2lc), c1=d+1, c2/c3 at m+8
    const size_t Sbase = ((size_t)bh*NCH + c)*Mc*Dc + (size_t)mh0*Dc;
    #pragma unroll
    for (int j = 0; j < 8; j++){
        int d0 = j*8 + lc*2;
        *(float2*)&g_S[Sbase + (size_t)(wm + lr)*Dc + d0]     = make_float2(acc[j][0], acc[j][1]);
        *(float2*)&g_S[Sbase + (size_t)(wm + 8 + lr)*Dc + d0] = make_float2(acc[j][2], acc[j][3]);
    }

    // z: exact scalar sums (threads 0..127, one m each)
    if (tid < 128){
        float zv = 0.f;
        #pragma unroll 8
        for (int t = 0; t < CHK; t++) zv += kt[t*KTP + tid];
        g_z[((size_t)bh*NCH + c)*Mc + mh0 + tid] = zv;
    }
}

// ============================================================
// K4: exclusive prefix over 32 chunks — one independent chain per thread.
// ============================================================
__global__ __launch_bounds__(256) void prefix_kernel()
{
    const int bh = blockIdx.x >> 6;          // 64 blocks per bh
    const int sl = blockIdx.x & 63;
    const int tid = threadIdx.x;
    const int e = (sl << 8) + tid;           // element in [0, Mc*Dc)

    size_t idx = (size_t)bh*NCH*Mc*Dc + e;
    float run = 0.f;
    #pragma unroll
    for (int c2 = 0; c2 < NCH; c2++){
        float tmp = g_S[idx]; g_S[idx] = run; run += tmp; idx += (size_t)Mc*Dc;
    }
    if (sl == 0){
        size_t zi = (size_t)bh*NCH*Mc + tid;
        float zr = 0.f;
        #pragma unroll
        for (int c2 = 0; c2 < NCH; c2++){
            float tmp = g_z[zi]; g_z[zi] = zr; zr += tmp; zi += Mc;
        }
    }
}

// ============================================================
// K5: mma.sync tf32 output kernel (unchanged from R9, __expf alpha).
// ============================================================
#define OP 68
__global__ __launch_bounds__(256,3) void out_kernel(const float* __restrict__ V,
                                                    float* __restrict__ Out)
{
    extern __shared__ float sm[];
    float* q_sm    = sm;            // [64 t][OP]  (aliased: A_sm after GEMM1)
    float* kp_sm   = sm + 64*OP;    // [64 s][OP]  (aliased: numI_sm)
    float* S_sm    = sm + 2*64*OP;  // [64 m][OP]  (aliased: v_sm)
    float* z_sm    = sm + 3*64*OP;          // [64]
    float* den_sm  = z_sm + 64;             // [64]
    float* denI_sm = den_sm + 64;           // [64]
    float* A_sm    = q_sm;
    float* numI_sm = kp_sm;
    float* v_sm    = S_sm;

    const int tid = threadIdx.x;
    const int w = tid >> 5, lane = tid & 31;
    const int tg = w & 3, ng = w >> 2;
    const int lr = lane >> 2, lc = lane & 3;
    const int bi = blockIdx.x;
    const int bh = bi >> 5, c = bi & 31;
    const int b = bh >> 3, h = bh & 7;
    const int lbase = c*CHK;
    const float alpha = RATIO * __expf(-g_kmax[bh]);

    const size_t qbase = ((size_t)bh*Lc + lbase)*Mc;
    const size_t Sb    = ((size_t)bh*NCH + c)*Mc*Dc;
    const size_t zbg   = ((size_t)bh*NCH + c)*Mc;
    const size_t vbase = (((size_t)b*Lc + lbase)*Hc + h)*Dc;

    const int t_lo = tg*16 + lr;
    const int t_hi = t_lo + 8;

    float acc[9][4];
    #pragma unroll
    for (int j = 0; j < 9; j++)
        #pragma unroll
        for (int r = 0; r < 4; r++) acc[j][r] = 0.f;

    // ================= GEMM1: loop over 4 m-tiles =================
    for (int m0 = 0; m0 < Mc; m0 += 64){
        __syncthreads();
        for (int i = tid; i < 1024; i += 256){
            int r = i >> 4, f4 = (i & 15)*4;
            float4 v = *(const float4*)&g_qp[qbase + (size_t)r*Mc + m0 + f4];
            *(float4*)&q_sm[r*OP + f4] =
                make_float4(tf32f(v.x), tf32f(v.y), tf32f(v.z), tf32f(v.w));
        }
        for (int i = tid; i < 1024; i += 256){
            int r = i >> 4, f4 = (i & 15)*4;
            float4 e = *(const float4*)&g_E[qbase + (size_t)r*Mc + m0 + f4];
            *(float4*)&kp_sm[r*OP + f4] =
                make_float4(tf32f(fmaf(alpha, e.x, BETA)), tf32f(fmaf(alpha, e.y, BETA)),
                            tf32f(fmaf(alpha, e.z, BETA)), tf32f(fmaf(alpha, e.w, BETA)));
        }
        for (int i = tid; i < 1024; i += 256){
            int r = i >> 4, f4 = (i & 15)*4;   // r = m row of tile
            float4 v = *(const float4*)&g_S[Sb + (size_t)(m0 + r)*Dc + f4];
            *(float4*)&S_sm[r*OP + f4] =
                make_float4(tf32f(v.x), tf32f(v.y), tf32f(v.z), tf32f(v.w));
        }
        if (tid < 64) z_sm[tid] = tf32f(g_z[zbg + m0 + tid]);
        __syncthreads();

        #pragma unroll
        for (int ks = 0; ks < 8; ks++){
            const int k0 = ks*8;
            const float* ar = &q_sm[t_lo*OP + k0 + lc];
            uint32_t a0 = __float_as_uint(ar[0]);
            uint32_t a1 = __float_as_uint(ar[8*OP]);
            uint32_t a2 = __float_as_uint(ar[4]);
            uint32_t a3 = __float_as_uint(ar[8*OP + 4]);
            if (ng == 0){
                #pragma unroll
                for (int j = 0; j < 8; j++){
                    uint32_t b0 = __float_as_uint(kp_sm[(j*8 + lr)*OP + k0 + lc]);
                    uint32_t b1 = __float_as_uint(kp_sm[(j*8 + lr)*OP + k0 + 4 + lc]);
                    mma_tf32(acc[j][0], acc[j][1], acc[j][2], acc[j][3],
                             a0, a1, a2, a3, b0, b1);
                }
            } else {
                #pragma unroll
                for (int j = 0; j < 8; j++){
                    uint32_t b0 = __float_as_uint(S_sm[(k0 + lc)*OP + j*8 + lr]);
                    uint32_t b1 = __float_as_uint(S_sm[(k0 + 4 + lc)*OP + j*8 + lr]);
                    mma_tf32(acc[j][0], acc[j][1], acc[j][2], acc[j][3],
                             a0, a1, a2, a3, b0, b1);
                }
                uint32_t b0 = (lr == 0) ? __float_as_uint(z_sm[k0 + lc]) : 0u;
                uint32_t b1 = (lr == 0) ? __float_as_uint(z_sm[k0 + 4 + lc]) : 0u;
                mma_tf32(acc[8][0], acc[8][1], acc[8][2], acc[8][3],
                         a0, a1, a2, a3, b0, b1);
            }
        }
    }
    __syncthreads();   // all GEMM1 reads done; aliases become writable

    // ================= epilogue =================
    if (ng == 0){
        float sum_lo = 0.f, sum_hi = 0.f;
        #pragma unroll
        for (int j = 0; j < 8; j++){
            int s0 = j*8 + lc*2;
            float v0 = (s0     <= t_lo) ? acc[j][0] : 0.f;
            float v1 = (s0 + 1 <= t_lo) ? acc[j][1] : 0.f;
            float v2 = (s0     <= t_hi) ? acc[j][2] : 0.f;
            float v3 = (s0 + 1 <= t_hi) ? acc[j][3] : 0.f;
            sum_lo += v0 + v1;
            sum_hi += v2 + v3;
            A_sm[t_lo*OP + s0]     = tf32f(v0);
            A_sm[t_lo*OP + s0 + 1] = tf32f(v1);
            A_sm[t_hi*OP + s0]     = tf32f(v2);
            A_sm[t_hi*OP + s0 + 1] = tf32f(v3);
        }
        sum_lo += __shfl_xor_sync(0xffffffffu, sum_lo, 1);
        sum_lo += __shfl_xor_sync(0xffffffffu, sum_lo, 2);
        sum_hi += __shfl_xor_sync(0xffffffffu, sum_hi, 1);
        sum_hi += __shfl_xor_sync(0xffffffffu, sum_hi, 2);
        if (lc == 0){ den_sm[t_lo] = sum_lo; den_sm[t_hi] = sum_hi; }
    } else {
        #pragma unroll
        for (int j = 0; j < 8; j++){
            int d0 = j*8 + lc*2;
            numI_sm[t_lo*OP + d0]     = acc[j][0];
            numI_sm[t_lo*OP + d0 + 1] = acc[j][1];
            numI_sm[t_hi*OP + d0]     = acc[j][2];
            numI_sm[t_hi*OP + d0 + 1] = acc[j][3];
        }
        if (lc == 0){ denI_sm[t_lo] = acc[8][0]; denI_sm[t_hi] = acc[8][2]; }
    }
    // stage V (tf32) into v_sm (aliases S_sm)
    for (int i = tid; i < 1024; i += 256){
        int s = i >> 4, f4 = (i & 15)*4;
        float4 v = *(const float4*)&V[vbase + (size_t)s*(Hc*Dc) + f4];
        *(float4*)&v_sm[s*OP + f4] =
            make_float4(tf32f(v.x), tf32f(v.y), tf32f(v.z), tf32f(v.w));
    }
    __syncthreads();

    // ================= GEMM2: num = numI + A V =================
    const int d0base = ng*32;
    float cc[4][4];
    #pragma unroll
    for (int j = 0; j < 4; j++){
        int d0 = d0base + j*8 + lc*2;
        cc[j][0] = numI_sm[t_lo*OP + d0];
        cc[j][1] = numI_sm[t_lo*OP + d0 + 1];
        cc[j][2] = numI_sm[t_hi*OP + d0];
        cc[j][3] = numI_sm[t_hi*OP + d0 + 1];
    }
    #pragma unroll
    for (int ks = 0; ks < 8; ks++){
        const int s0 = ks*8;
        const float* ar = &A_sm[t_lo*OP + s0 + lc];
        uint32_t a0 = __float_as_uint(ar[0]);
        uint32_t a1 = __float_as_uint(ar[8*OP]);
        uint32_t a2 = __float_as_uint(ar[4]);
        uint32_t a3 = __float_as_uint(ar[8*OP + 4]);
        #pragma unroll
        for (int j = 0; j < 4; j++){
            int d0 = d0base + j*8;
            uint32_t b0 = __float_as_uint(v_sm[(s0 + lc)*OP + d0 + lr]);
            uint32_t b1 = __float_as_uint(v_sm[(s0 + 4 + lc)*OP + d0 + lr]);
            mma_tf32(cc[j][0], cc[j][1], cc[j][2], cc[j][3],
                     a0, a1, a2, a3, b0, b1);
        }
    }

    // ================= normalize + store =================
    float denL = den_sm[t_lo] + denI_sm[t_lo];
    float denH = den_sm[t_hi] + denI_sm[t_hi];
    if (fabsf(denL) <= 1e-6f) denL += 2e-6f;
    if (fabsf(denH) <= 1e-6f) denH += 2e-6f;
    float invL = 1.0f / denL;
    float invH = 1.0f / denH;

    float* orowL = Out + (((size_t)b*Lc + lbase + t_lo)*Hc + h)*Dc;
    float* orowH = Out + (((size_t)b*Lc + lbase + t_hi)*Hc + h)*Dc;
    #pragma unroll
    for (int j = 0; j < 4; j++){
        int d0 = d0base + j*8 + lc*2;
        *(float2*)&orowL[d0] = make_float2(cc[j][0]*invL, cc[j][1]*invL);
        *(float2*)&orowH[d0] = make_float2(cc[j][2]*invH, cc[j][3]*invH);
    }
}

// ============================================================
extern "C" void kernel_launch(void* const* d_in, const int* in_sizes, int n_in,
                              void* d_out, int out_size)
{
    const float* Q = (const float*)d_in[0];
    const float* K = (const float*)d_in[1];
    const float* V = (const float*)d_in[2];
    const float* P = (const float*)d_in[3];
    float* O = (float*)d_out;

    const int SM1 = (64*PT_S + 64*XT_S + 64) * 4;   // ~84 KB
    const int SM3 = (64*KTP + 64*VTP) * 4;          // ~52 KB
    const int SM5 = (3*64*OP + 64*3) * 4;           // ~53 KB

    cudaFuncSetAttribute(feat_kernel,  cudaFuncAttributeMaxDynamicSharedMemorySize, SM1);
    cudaFuncSetAttribute(state_kernel, cudaFuncAttributeMaxDynamicSharedMemorySize, SM3);
    cudaFuncSetAttribute(out_kernel,   cudaFuncAttributeMaxDynamicSharedMemorySize, SM5);

    init_kernel<<<1, 32>>>();
    feat_kernel<<<NROWS/128, 256, SM1>>>(Q, P, 1);
    feat_kernel<<<NROWS/128, 256, SM1>>>(K, P, 0);
    state_kernel<<<BH*NCH*2, 256, SM3>>>(V);
    prefix_kernel<<<BH*64, 256>>>();
    out_kernel<<<BH*NCH, 256, SM5>>>(V, O);
}